// round 10
// baseline (speedup 1.0000x reference)
#include <cuda_runtime.h>
#include <cuda_bf16.h>

// Sparsemax rows of 2048 fp32 — persistent CTA-per-row, register prefetch,
// ONE barrier per row, no atomics, no serialized solve.
//  - gather: each warp ballot-compacts its candidates (z > THETA) into its own
//    12-slot region of a double-buffered 96-slot smem array (no shared counter;
//    overflow writes a +INF sentinel -> fallback).
//  - solve: ALL warps redundantly run Michelot over the 96 slots via shuffles;
//    tau >= THETA self-certifies exactness (KKT: discarded <= THETA <= tau).
//  - store: coalesced streaming float4 projection write.
// Fallback (uniform across block, prob ~2e-5/row): full-block Michelot.

#define ROWLEN  2048
#define THREADS 256
#define VPT     (ROWLEN / THREADS)   // 8
#define NWARP   (THREADS / 32)       // 8
#define F4PROW  (ROWLEN / 4)         // 512
#define SLOTS   12                   // candidate slots per warp
#define CAPT    (NWARP * SLOTS)      // 96
#define THETA   2.25f
#define NEG_INF (-3.0e38f)
#define SENT    (3.0e38f)
#define FULLM   0xffffffffu
#define OCC     6
#define GRID_CTAS (148 * OCC)

__global__ __launch_bounds__(THREADS, OCC)
void sparsemax_kernel(const float* __restrict__ z, float* __restrict__ out, int rows) {
    const float4* __restrict__ z4   = reinterpret_cast<const float4*>(z);
    float4* __restrict__       out4 = reinterpret_cast<float4*>(out);
    const int tid  = threadIdx.x;
    const int lane = tid & 31;
    const int wid  = tid >> 5;
    const long long stride = gridDim.x;

    __shared__ float s_cand[2][CAPT];
    __shared__ float s_red[NWARP];
    __shared__ float s_cnt[NWARP];
    __shared__ float s_btau;

    long long r = blockIdx.x;
    if (r >= rows) return;

    // prime pipeline
    float4 a = __ldcs(&z4[r * F4PROW + tid]);
    float4 b = __ldcs(&z4[r * F4PROW + THREADS + tid]);

    int p = 0;
    const unsigned lt = (1u << lane) - 1u;

    #pragma unroll 1
    while (true) {
        const long long rn = r + stride;
        float v[VPT] = {a.x, a.y, a.z, a.w, b.x, b.y, b.z, b.w};

        // ---- clear own slot region, then ballot-compact candidates ----
        float* wbuf = &s_cand[p][wid * SLOTS];
        if (lane < SLOTS) wbuf[lane] = NEG_INF;
        __syncwarp();
        int base = 0;
        #pragma unroll
        for (int i = 0; i < VPT; i++) {
            bool c = v[i] > THETA;
            unsigned ball = __ballot_sync(FULLM, c);
            if (c) {
                int idx = base + __popc(ball & lt);
                if (idx < SLOTS) wbuf[idx] = v[i];
            }
            base += __popc(ball);
        }
        __syncwarp();
        if (base > SLOTS && lane == 0) wbuf[SLOTS - 1] = SENT;  // overflow sentinel

        // ---- prefetch next row before the barrier (hides DRAM latency) ----
        if (rn < rows) {
            a = __ldcs(&z4[rn * F4PROW + tid]);
            b = __ldcs(&z4[rn * F4PROW + THREADS + tid]);
        }
        __syncthreads();   // all warps' gathers into s_cand[p] complete

        // ---- every warp redundantly solves Michelot on the 96 slots ----
        const float* cb = s_cand[p];
        float c0 = cb[lane];
        float c1 = cb[lane + 32];
        float c2 = cb[lane + 64];
        float tau;
        bool ok;
        {
            float mx = fmaxf(fmaxf(c0, c1), c2);
            float s0 = 0.0f, n0 = 0.0f;
            if (c0 > NEG_INF) { s0 += c0; n0 += 1.0f; }
            if (c1 > NEG_INF) { s0 += c1; n0 += 1.0f; }
            if (c2 > NEG_INF) { s0 += c2; n0 += 1.0f; }
            #pragma unroll
            for (int o = 16; o > 0; o >>= 1) {
                mx  = fmaxf(mx, __shfl_xor_sync(FULLM, mx, o));
                s0 += __shfl_xor_sync(FULLM, s0, o);
                n0 += __shfl_xor_sync(FULLM, n0, o);
            }
            bool bad = (mx >= 1.0e37f) || (n0 == 0.0f);
            tau = (s0 - 1.0f) / (n0 > 0.0f ? n0 : 1.0f);
            int prev = -1;
            #pragma unroll 1
            for (int it = 0; it < 32 && !bad; it++) {
                float s = 0.0f, cnt = 0.0f;
                bool a0 = c0 > tau, a1 = c1 > tau, a2 = c2 > tau;
                s += a0 ? c0 : 0.0f;  cnt += a0 ? 1.0f : 0.0f;
                s += a1 ? c1 : 0.0f;  cnt += a1 ? 1.0f : 0.0f;
                s += a2 ? c2 : 0.0f;  cnt += a2 ? 1.0f : 0.0f;
                #pragma unroll
                for (int o = 16; o > 0; o >>= 1) {
                    s   += __shfl_xor_sync(FULLM, s, o);
                    cnt += __shfl_xor_sync(FULLM, cnt, o);
                }
                if (cnt == 0.0f) break;
                tau = (s - 1.0f) / cnt;
                int k = (int)cnt;
                if (k == prev) break;
                prev = k;
            }
            ok = !bad && (tau >= THETA);   // uniform across all warps (same data)
        }

        if (!ok) {
            // ---- fallback: full-block Michelot (uniform entry, prob ~0) ----
            {
                float s = 0.0f;
                #pragma unroll
                for (int i = 0; i < VPT; i++) s += v[i];
                #pragma unroll
                for (int o = 16; o > 0; o >>= 1) s += __shfl_xor_sync(FULLM, s, o);
                if (lane == 0) s_red[wid] = s;
                __syncthreads();
                if (tid == 0) {
                    float tot = 0.0f;
                    #pragma unroll
                    for (int w = 0; w < NWARP; w++) tot += s_red[w];
                    s_btau = (tot - 1.0f) * (1.0f / (float)ROWLEN);
                }
                __syncthreads();
                tau = s_btau;
            }
            int k_prev = ROWLEN;
            #pragma unroll 1
            for (int it = 0; it < 64; it++) {
                float s = 0.0f, cf = 0.0f;
                #pragma unroll
                for (int i = 0; i < VPT; i++) {
                    bool act = v[i] > tau;
                    s  += act ? v[i] : 0.0f;
                    cf += act ? 1.0f : 0.0f;
                }
                #pragma unroll
                for (int o = 16; o > 0; o >>= 1) {
                    s  += __shfl_xor_sync(FULLM, s, o);
                    cf += __shfl_xor_sync(FULLM, cf, o);
                }
                if (lane == 0) { s_red[wid] = s; s_cnt[wid] = cf; }
                __syncthreads();
                if (tid == 0) {
                    float ts = 0.0f, tc = 0.0f;
                    #pragma unroll
                    for (int w = 0; w < NWARP; w++) { ts += s_red[w]; tc += s_cnt[w]; }
                    s_btau = (ts - 1.0f) / tc;
                    s_cnt[0] = tc;
                }
                __syncthreads();
                tau = s_btau;
                int k = (int)s_cnt[0];
                __syncthreads();
                if (k == k_prev) break;
                k_prev = k;
            }
        }

        // ---- coalesced streaming projection store ----
        float4 o0, o1;
        o0.x = fmaxf(v[0] - tau, 0.0f);
        o0.y = fmaxf(v[1] - tau, 0.0f);
        o0.z = fmaxf(v[2] - tau, 0.0f);
        o0.w = fmaxf(v[3] - tau, 0.0f);
        o1.x = fmaxf(v[4] - tau, 0.0f);
        o1.y = fmaxf(v[5] - tau, 0.0f);
        o1.z = fmaxf(v[6] - tau, 0.0f);
        o1.w = fmaxf(v[7] - tau, 0.0f);
        __stcs(&out4[r * F4PROW + tid],           o0);
        __stcs(&out4[r * F4PROW + THREADS + tid], o1);

        if (rn >= rows) break;
        r = rn;
        p ^= 1;
    }
}

extern "C" void kernel_launch(void* const* d_in, const int* in_sizes, int n_in,
                              void* d_out, int out_size) {
    const float* z = (const float*)d_in[0];
    float* out = (float*)d_out;
    int rows = in_sizes[0] / ROWLEN;
    int grid = GRID_CTAS < rows ? GRID_CTAS : rows;
    sparsemax_kernel<<<grid, THREADS>>>(z, out, rows);
}

// round 11
// speedup vs baseline: 1.3966x; 1.3966x over previous
#include <cuda_runtime.h>
#include <cuda_bf16.h>

// Sparsemax rows of 2048 fp32 — persistent CTA-per-row, software-pipelined
// with skew 2 and ONE barrier per row:
//   iter i:  gather(row i) -> cand[i&1]          (all warps, fresh cached loads)
//            solve(row i-1) by warp 0 only       (from cand[(i-1)&1])
//            store(row i-2) re-read from L1      (warps 1-7 overlap the solve)
//            __syncthreads()
// Static THETA: candidates z > THETA; solved tau >= THETA self-certifies
// exactness via KKT (every discarded element <= THETA <= tau).
// Rare fallback: warp-0 multi-pass Michelot re-reading the row from L2.

#define ROWLEN  2048
#define THREADS 256
#define NWARP   (THREADS / 32)
#define F4PROW  (ROWLEN / 4)     // 512
#define CAP     64
#define THETA   2.25f
#define NEG_INF (-3.0e38f)
#define FULLM   0xffffffffu
#define OCC     8
#define GRID_CTAS (148 * OCC)

__global__ __launch_bounds__(THREADS, OCC)
void sparsemax_kernel(const float* __restrict__ z, float* __restrict__ out, int rows) {
    const float4* __restrict__ z4 = reinterpret_cast<const float4*>(z);
    float4* __restrict__       o4 = reinterpret_cast<float4*>(out);
    const int tid  = threadIdx.x;
    const int lane = tid & 31;
    const int wid  = tid >> 5;

    __shared__ float s_cand[2][CAP];
    __shared__ int   s_n[2];
    __shared__ float s_tau[2];

    const int r0     = blockIdx.x;
    const int stride = gridDim.x;
    if (r0 >= rows) return;
    const int G = (rows - 1 - r0) / stride + 1;   // rows owned by this CTA

    if (tid == 0) { s_n[0] = 0; s_n[1] = 0; }
    __syncthreads();

    #pragma unroll 1
    for (int i = 0; i < G + 2; i++) {
        // ---- gather row i: cached loads feed candidate filter (and stay in L1) ----
        if (i < G) {
            const float4* zr = &z4[(long long)(r0 + i * stride) * F4PROW];
            int*   np = &s_n[i & 1];
            float* cb = s_cand[i & 1];
            float4 qa = __ldg(&zr[tid]);
            float4 qb = __ldg(&zr[tid + THREADS]);
            float m = fmaxf(fmaxf(fmaxf(qa.x, qa.y), fmaxf(qa.z, qa.w)),
                            fmaxf(fmaxf(qb.x, qb.y), fmaxf(qb.z, qb.w)));
            if (m > THETA) {
                if (qa.x > THETA) { int ix = atomicAdd(np, 1); if (ix < CAP) cb[ix] = qa.x; }
                if (qa.y > THETA) { int ix = atomicAdd(np, 1); if (ix < CAP) cb[ix] = qa.y; }
                if (qa.z > THETA) { int ix = atomicAdd(np, 1); if (ix < CAP) cb[ix] = qa.z; }
                if (qa.w > THETA) { int ix = atomicAdd(np, 1); if (ix < CAP) cb[ix] = qa.w; }
                if (qb.x > THETA) { int ix = atomicAdd(np, 1); if (ix < CAP) cb[ix] = qb.x; }
                if (qb.y > THETA) { int ix = atomicAdd(np, 1); if (ix < CAP) cb[ix] = qb.y; }
                if (qb.z > THETA) { int ix = atomicAdd(np, 1); if (ix < CAP) cb[ix] = qb.z; }
                if (qb.w > THETA) { int ix = atomicAdd(np, 1); if (ix < CAP) cb[ix] = qb.w; }
            }
        }

        // ---- warp 0: solve row i-1 (candidates visible via previous barrier) ----
        if (wid == 0 && i >= 1 && i <= G) {
            const int q = (i - 1) & 1;
            const int n = s_n[q];
            float c0 = (lane < n)      ? s_cand[q][lane]      : NEG_INF;
            float c1 = (lane + 32 < n) ? s_cand[q][lane + 32] : NEG_INF;
            float s0 = (c0 > NEG_INF ? c0 : 0.0f) + (c1 > NEG_INF ? c1 : 0.0f);
            #pragma unroll
            for (int o = 16; o > 0; o >>= 1) s0 += __shfl_xor_sync(FULLM, s0, o);
            int n0 = n > 0 ? (n <= CAP ? n : CAP) : 1;
            float tau = (s0 - 1.0f) / (float)n0;
            int prev = -1;
            #pragma unroll 1
            for (int it = 0; it < 32; it++) {
                float s = 0.0f, cnt = 0.0f;
                bool a0 = c0 > tau, a1 = c1 > tau;
                s += a0 ? c0 : 0.0f;  cnt += a0 ? 1.0f : 0.0f;
                s += a1 ? c1 : 0.0f;  cnt += a1 ? 1.0f : 0.0f;
                #pragma unroll
                for (int o = 16; o > 0; o >>= 1) {
                    s   += __shfl_xor_sync(FULLM, s, o);
                    cnt += __shfl_xor_sync(FULLM, cnt, o);
                }
                if (cnt == 0.0f) break;
                tau = (s - 1.0f) / cnt;
                int k = (int)cnt;
                if (k == prev) break;
                prev = k;
            }
            bool ok = (n > 0 && n <= CAP && tau >= THETA);

            if (!ok) {
                // rare fallback: warp-level multi-pass Michelot, row from L2
                const float4* zr = &z4[(long long)(r0 + (i - 1) * stride) * F4PROW];
                float s = 0.0f;
                #pragma unroll 4
                for (int j = 0; j < 16; j++) {
                    float4 q4 = __ldg(&zr[lane + 32 * j]);
                    s += (q4.x + q4.y) + (q4.z + q4.w);
                }
                #pragma unroll
                for (int o = 16; o > 0; o >>= 1) s += __shfl_xor_sync(FULLM, s, o);
                tau = (s - 1.0f) * (1.0f / (float)ROWLEN);
                int k_prev = ROWLEN;
                #pragma unroll 1
                for (int it = 0; it < 64; it++) {
                    float ss = 0.0f, cc = 0.0f;
                    #pragma unroll 4
                    for (int j = 0; j < 16; j++) {
                        float4 q4 = __ldg(&zr[lane + 32 * j]);
                        if (q4.x > tau) { ss += q4.x; cc += 1.0f; }
                        if (q4.y > tau) { ss += q4.y; cc += 1.0f; }
                        if (q4.z > tau) { ss += q4.z; cc += 1.0f; }
                        if (q4.w > tau) { ss += q4.w; cc += 1.0f; }
                    }
                    #pragma unroll
                    for (int o = 16; o > 0; o >>= 1) {
                        ss += __shfl_xor_sync(FULLM, ss, o);
                        cc += __shfl_xor_sync(FULLM, cc, o);
                    }
                    if (cc == 0.0f) break;
                    tau = (ss - 1.0f) / cc;
                    int k = (int)cc;
                    if (k == k_prev) break;
                    k_prev = k;
                }
            }
            if (lane == 0) { s_tau[q] = tau; s_n[q] = 0; }
        }

        // ---- store row i-2: re-read from L1 (loaded 2 iters ago), project ----
        if (i >= 2) {
            const float tau = s_tau[i & 1];   // slot (i-2)&1, written iter i-1
            const long long rs = (long long)(r0 + (i - 2) * stride) * F4PROW;
            const float4* zr = &z4[rs];
            float4*       orow = &o4[rs];
            float4 qa = __ldg(&zr[tid]);
            float4 qb = __ldg(&zr[tid + THREADS]);
            float4 oa, ob;
            oa.x = fmaxf(qa.x - tau, 0.0f);
            oa.y = fmaxf(qa.y - tau, 0.0f);
            oa.z = fmaxf(qa.z - tau, 0.0f);
            oa.w = fmaxf(qa.w - tau, 0.0f);
            ob.x = fmaxf(qb.x - tau, 0.0f);
            ob.y = fmaxf(qb.y - tau, 0.0f);
            ob.z = fmaxf(qb.z - tau, 0.0f);
            ob.w = fmaxf(qb.w - tau, 0.0f);
            __stcs(&orow[tid],           oa);
            __stcs(&orow[tid + THREADS], ob);
        }

        __syncthreads();   // the ONE barrier per row
    }
}

extern "C" void kernel_launch(void* const* d_in, const int* in_sizes, int n_in,
                              void* d_out, int out_size) {
    const float* z = (const float*)d_in[0];
    float* out = (float*)d_out;
    int rows = in_sizes[0] / ROWLEN;
    int grid = GRID_CTAS < rows ? GRID_CTAS : rows;
    sparsemax_kernel<<<grid, THREADS>>>(z, out, rows);
}